// round 14
// baseline (speedup 1.0000x reference)
#include <cuda_runtime.h>
#include <cuda_bf16.h>
#include <cstdint>

// ---------------------------------------------------------------------------
// Problem constants: B=64, S=20, E=512, H=512, V=32000, C=1000
//   D1 = 11264, virtual K1 = 11776 = [enc|word|persona|h0], 4H = 2048
// ---------------------------------------------------------------------------
#define Bsz   64
#define Hdim  512
#define G4H   2048
#define Vdim  32000
#define K1v   11776

static __device__ float g_zpart[8 * Bsz * G4H];            // 4.2 MB (8 slices)
static __device__ float g_cbuf[2][Bsz * Hdim];
static __device__ float g_logits[Bsz * Vdim];              // 8.2 MB
static __device__ __nv_bfloat16 g_x1h[Bsz * K1v];          // layer-1 A hi
static __device__ __nv_bfloat16 g_x1l[Bsz * K1v];          // layer-1 A lo
static __device__ __nv_bfloat16 g_hh[2][Bsz * Hdim];       // h bf16 hi
static __device__ __nv_bfloat16 g_hl[2][Bsz * Hdim];       // h bf16 lo
static __device__ int g_bar1 = 0;                          // grid barrier arrive
static __device__ int g_bar2 = 0;                          // grid barrier depart

__device__ __forceinline__ float sigmoidf_fast(float x) {
    return 1.0f / (1.0f + __expf(-x));
}
__device__ __forceinline__ uint32_t smem_u32(const void* p) {
    uint32_t a;
    asm("{ .reg .u64 t; cvta.to.shared.u64 t, %1; cvt.u32.u64 %0, t; }"
        : "=r"(a) : "l"(p));
    return a;
}
__device__ __forceinline__ void ldsm4(uint32_t* r, uint32_t addr) {
    asm volatile("ldmatrix.sync.aligned.m8n8.x4.shared.b16 {%0,%1,%2,%3}, [%4];"
                 : "=r"(r[0]), "=r"(r[1]), "=r"(r[2]), "=r"(r[3]) : "r"(addr));
}
__device__ __forceinline__ void ldsm4t(uint32_t* r, uint32_t addr) {
    asm volatile("ldmatrix.sync.aligned.m8n8.x4.trans.shared.b16 {%0,%1,%2,%3}, [%4];"
                 : "=r"(r[0]), "=r"(r[1]), "=r"(r[2]), "=r"(r[3]) : "r"(addr));
}
__device__ __forceinline__ void mma16816(float* d, const uint32_t* a,
                                         uint32_t b0, uint32_t b1) {
    asm volatile(
        "mma.sync.aligned.m16n8k16.row.col.f32.bf16.bf16.f32 "
        "{%0,%1,%2,%3}, {%4,%5,%6,%7}, {%8,%9}, {%0,%1,%2,%3};"
        : "+f"(d[0]), "+f"(d[1]), "+f"(d[2]), "+f"(d[3])
        : "r"(a[0]), "r"(a[1]), "r"(a[2]), "r"(a[3]), "r"(b0), "r"(b1));
}
// Dekker split of 2 floats -> packed bf16x2 hi + lo (rn-exact vs element-wise)
__device__ __forceinline__ void dek2(float x, float y, uint32_t& hp, uint32_t& lp) {
    asm("cvt.rn.bf16x2.f32 %0, %1, %2;" : "=r"(hp) : "f"(y), "f"(x));
    float fx = __uint_as_float(hp << 16);
    float fy = __uint_as_float(hp & 0xFFFF0000u);
    asm("cvt.rn.bf16x2.f32 %0, %1, %2;" : "=r"(lp) : "f"(y - fy), "f"(x - fx));
}

// ---------------------------------------------------------------------------
// xconv: build layer-1 A = [enc|word|persona[spk]|h0] as bf16 hi/lo planes.
// ---------------------------------------------------------------------------
__global__ void xconv_kernel(const float* __restrict__ enc,
                             const float* __restrict__ word,
                             const float* __restrict__ persona,
                             const float* __restrict__ h0,
                             const int* __restrict__ speaker,
                             __nv_bfloat16* __restrict__ xh,
                             __nv_bfloat16* __restrict__ xl)
{
    int idx = blockIdx.x * 128 + threadIdx.x;      // < 94208
    int row = idx / (K1v / 8);
    int q = (idx - row * (K1v / 8)) * 8;
    const float* p;
    if (q < 10240)       p = enc + (long long)row * 10240 + q;
    else if (q < 10752)  p = word + (long long)row * 512 + (q - 10240);
    else if (q < 11264)  p = persona + (long long)speaker[row] * 512 + (q - 10752);
    else                 p = h0 + (long long)row * 512 + (q - 11264);
    float4 a = *reinterpret_cast<const float4*>(p);
    float4 b = *reinterpret_cast<const float4*>(p + 4);
    uint32_t h0p, l0p, h1p, l1p, h2p, l2p, h3p, l3p;
    dek2(a.x, a.y, h0p, l0p);
    dek2(a.z, a.w, h1p, l1p);
    dek2(b.x, b.y, h2p, l2p);
    dek2(b.z, b.w, h3p, l3p);
    long long o = (long long)row * K1v + q;
    *reinterpret_cast<uint4*>(xh + o) = make_uint4(h0p, h1p, h2p, h3p);
    *reinterpret_cast<uint4*>(xl + o) = make_uint4(l0p, l1p, l2p, l3p);
}

// ---------------------------------------------------------------------------
// bf16 Dekker-split warp-MMA GEMM with DEPTH-2 register prefetch, optionally
// FUSED with the LSTM gate reduction via an in-kernel grid barrier (NSL > 0;
// requires grid <= 296 co-resident CTAs at 2 CTA/SM).
// A: preconverted bf16 hi/lo planes. W: fp32, converted in-loader.
// Pipeline: at iter t, issue gmem loads for tile t+2 (reg set t&1) while
// tile t+1's loads (issued at t-1) drain; store t+1 to smem at end of t.
// ---------------------------------------------------------------------------
template<int XSTRIDE, bool WRAP, int NSL>
__global__ __launch_bounds__(128, 2) void mma_gemm_kernel(
    const __nv_bfloat16* __restrict__ Xh, const __nv_bfloat16* __restrict__ Xl,
    const float* __restrict__ Wa, const float* __restrict__ Wb, int wsplit,
    int kc, int N, float* __restrict__ Zall,
    const float* __restrict__ bias, const float* __restrict__ c_prev,
    float* __restrict__ c_new,
    uint32_t* __restrict__ hh_out, uint32_t* __restrict__ hl_out,
    float* __restrict__ h_mir, float* __restrict__ c_mir)
{
    __shared__ __align__(16) __nv_bfloat16 Ah[2][64][40];  // stride 80B
    __shared__ __align__(16) __nv_bfloat16 Al[2][64][40];
    __shared__ __align__(16) __nv_bfloat16 Bh[2][32][72];  // stride 144B
    __shared__ __align__(16) __nv_bfloat16 Bl[2][32][72];

    const int tid = threadIdx.x;
    const int lane = tid & 31;
    const int warp = tid >> 5;
    const int n0 = blockIdx.x * 64;
    const int sp = blockIdx.y;
    const int k0 = sp * kc;
    float* Z = Zall + (long long)sp * 64 * N;

    const int xm = tid >> 1;
    const int xh2 = (tid & 1) * 16;
    const __nv_bfloat16* xhp = Xh + (long long)xm * XSTRIDE;
    const __nv_bfloat16* xlp = Xl + (long long)xm * XSTRIDE;
    const int bk = tid >> 2;
    const int bn = (tid & 3) * 16;

    // two register sets for depth-2 pipelining: tile i lives in set i&1
    uint4 avh0[2], avh1[2], avl0[2], avl1[2];
    float4 br[2][4];
    auto loadA = [&](int t, int s) {
        int kg = k0 + t * 32 + xh2;
        if (WRAP) kg &= 511;
        avh0[s] = *reinterpret_cast<const uint4*>(xhp + kg);
        avh1[s] = *reinterpret_cast<const uint4*>(xhp + kg + 8);
        avl0[s] = *reinterpret_cast<const uint4*>(xlp + kg);
        avl1[s] = *reinterpret_cast<const uint4*>(xlp + kg + 8);
    };
    auto loadB = [&](int t, int s) {
        int r = k0 + t * 32 + bk;
        const float* p = (r < wsplit) ? (Wa + (long long)r * N)
                                      : (Wb + (long long)(r - wsplit) * N);
#pragma unroll
        for (int i = 0; i < 4; i++)
            br[s][i] = *reinterpret_cast<const float4*>(p + n0 + bn + i * 4);
    };
    auto storeA = [&](int b, int s) {
        *reinterpret_cast<uint4*>(&Ah[b][xm][xh2])     = avh0[s];
        *reinterpret_cast<uint4*>(&Ah[b][xm][xh2 + 8]) = avh1[s];
        *reinterpret_cast<uint4*>(&Al[b][xm][xh2])     = avl0[s];
        *reinterpret_cast<uint4*>(&Al[b][xm][xh2 + 8]) = avl1[s];
    };
    auto storeB = [&](int b, int s) {
#pragma unroll
        for (int i = 0; i < 4; i++) {
            float4 v = br[s][i];
            uint32_t h01, l01, h23, l23;
            dek2(v.x, v.y, h01, l01);
            dek2(v.z, v.w, h23, l23);
            *reinterpret_cast<uint2*>(&Bh[b][bk][bn + i * 4]) = make_uint2(h01, h23);
            *reinterpret_cast<uint2*>(&Bl[b][bk][bn + i * 4]) = make_uint2(l01, l23);
        }
    };

    float acc[4][2][4];
#pragma unroll
    for (int mt = 0; mt < 4; mt++)
#pragma unroll
        for (int nt = 0; nt < 2; nt++)
#pragma unroll
            for (int e = 0; e < 4; e++) acc[mt][nt][e] = 0.0f;

    const int NT = kc >> 5;     // BK = 32
    // prologue: tile 0 -> smem buf0; tile 1 loads in flight (reg set 1)
    loadA(0, 0); loadB(0, 0);
    storeA(0, 0); storeB(0, 0);
    __syncthreads();
    if (NT > 1) { loadA(1, 1); loadB(1, 1); }

    const int nw = warp * 16;
    const int lr = lane & 15;
    const int lc = (lane >> 4) * 8;

    for (int t = 0; t < NT; t++) {
        const int buf = t & 1;
        if (t + 2 < NT) { loadA(t + 2, t & 1); loadB(t + 2, t & 1); }

#pragma unroll
        for (int s = 0; s < 2; s++) {
            uint32_t bhf[4], blf[4];
            ldsm4t(bhf, smem_u32(&Bh[buf][s * 16 + lr][nw + lc]));
            ldsm4t(blf, smem_u32(&Bl[buf][s * 16 + lr][nw + lc]));
#pragma unroll
            for (int mt = 0; mt < 4; mt++) {
                uint32_t ahf[4], alf[4];
                ldsm4(ahf, smem_u32(&Ah[buf][mt * 16 + lr][s * 16 + lc]));
                ldsm4(alf, smem_u32(&Al[buf][mt * 16 + lr][s * 16 + lc]));
                mma16816(acc[mt][0], ahf, bhf[0], bhf[1]);
                mma16816(acc[mt][1], ahf, bhf[2], bhf[3]);
                mma16816(acc[mt][0], ahf, blf[0], blf[1]);
                mma16816(acc[mt][1], ahf, blf[2], blf[3]);
                mma16816(acc[mt][0], alf, bhf[0], bhf[1]);
                mma16816(acc[mt][1], alf, bhf[2], bhf[3]);
            }
        }
        if (t + 1 < NT) { storeA((t + 1) & 1, (t + 1) & 1); storeB((t + 1) & 1, (t + 1) & 1); }
        __syncthreads();
    }

    // GEMM epilogue: write split-K partials
#pragma unroll
    for (int mt = 0; mt < 4; mt++)
#pragma unroll
        for (int nt = 0; nt < 2; nt++) {
            int row = mt * 16 + (lane >> 2);
            int col = n0 + nw + nt * 8 + (lane & 3) * 2;
            *reinterpret_cast<float2*>(&Z[(long long)row * N + col]) =
                make_float2(acc[mt][nt][0], acc[mt][nt][1]);
            *reinterpret_cast<float2*>(&Z[(long long)(row + 8) * N + col]) =
                make_float2(acc[mt][nt][2], acc[mt][nt][3]);
        }

    if (NSL > 0) {
        // ---- grid barrier (all CTAs co-resident by construction) ----
        const int G = gridDim.x * gridDim.y;
        __threadfence();
        __syncthreads();
        if (tid == 0) {
            atomicAdd(&g_bar1, 1);
            while (*(volatile int*)&g_bar1 < G) {}
        }
        __syncthreads();
        __threadfence();

        // ---- phase 2: gates over all slices ----
        int gid = (blockIdx.y * gridDim.x + blockIdx.x) * 128 + tid;
        if (gid < Bsz * (Hdim / 2)) {
            int bt = gid >> 8;
            int j = (gid & 255) * 2;
            float2 zi = *reinterpret_cast<const float2*>(bias + j);
            float2 zf = *reinterpret_cast<const float2*>(bias + 512 + j);
            float2 zg = *reinterpret_cast<const float2*>(bias + 1024 + j);
            float2 zo = *reinterpret_cast<const float2*>(bias + 1536 + j);
            const float* p = Zall + (long long)bt * G4H + j;
#pragma unroll
            for (int s = 0; s < NSL; s++) {
                const float* q = p + (long long)s * Bsz * G4H;
                float2 a = *reinterpret_cast<const float2*>(q);
                float2 b = *reinterpret_cast<const float2*>(q + 512);
                float2 c = *reinterpret_cast<const float2*>(q + 1024);
                float2 d = *reinterpret_cast<const float2*>(q + 1536);
                zi.x += a.x; zi.y += a.y;
                zf.x += b.x; zf.y += b.y;
                zg.x += c.x; zg.y += c.y;
                zo.x += d.x; zo.y += d.y;
            }
            int idx = bt * Hdim + j;
            float2 cp = *reinterpret_cast<const float2*>(c_prev + idx);
            float2 cv, hv;
            cv.x = sigmoidf_fast(zf.x) * cp.x + sigmoidf_fast(zi.x) * fmaxf(zg.x, 0.0f);
            cv.y = sigmoidf_fast(zf.y) * cp.y + sigmoidf_fast(zi.y) * fmaxf(zg.y, 0.0f);
            hv.x = sigmoidf_fast(zo.x) * fmaxf(cv.x, 0.0f);
            hv.y = sigmoidf_fast(zo.y) * fmaxf(cv.y, 0.0f);
            *reinterpret_cast<float2*>(c_new + idx) = cv;
            uint32_t hp, lp;
            dek2(hv.x, hv.y, hp, lp);
            hh_out[gid] = hp;
            hl_out[gid] = lp;
            if (h_mir) {
                *reinterpret_cast<float2*>(h_mir + idx) = hv;
                *reinterpret_cast<float2*>(c_mir + idx) = cv;
            }
        }

        // ---- depart barrier + counter reset (CTA (0,0)) ----
        __threadfence();
        __syncthreads();
        if (tid == 0) {
            atomicAdd(&g_bar2, 1);
            if (blockIdx.x == 0 && blockIdx.y == 0) {
                while (*(volatile int*)&g_bar2 < G) {}
                atomicExch(&g_bar1, 0);
                atomicExch(&g_bar2, 0);
            }
        }
    }
}

// ---------------------------------------------------------------------------
// Softmax over V=32000 per batch row
// ---------------------------------------------------------------------------
__global__ void softmax_kernel(const float* __restrict__ L,
                               const float* __restrict__ bd,
                               float* __restrict__ out)
{
    const int V = Vdim;
    int b = blockIdx.x;
    int tid = threadIdx.x;
    const float* r0 = L + (long long)b * V;

    float m = -1e30f, s = 0.0f;
    for (int v = tid; v < V; v += 512) {
        float val = r0[v] + bd[v];
        float nm = fmaxf(m, val);
        s = s * __expf(m - nm) + __expf(val - nm);
        m = nm;
    }
    __shared__ float sm[512], ss[512];
    sm[tid] = m; ss[tid] = s;
    __syncthreads();
    for (int st = 256; st > 0; st >>= 1) {
        if (tid < st) {
            float m2 = sm[tid + st], s2 = ss[tid + st];
            float nm = fmaxf(sm[tid], m2);
            ss[tid] = ss[tid] * __expf(sm[tid] - nm) + s2 * __expf(m2 - nm);
            sm[tid] = nm;
        }
        __syncthreads();
    }
    float M = sm[0];
    float Sinv = 1.0f / ss[0];
    for (int v = tid; v < V; v += 512) {
        float val = r0[v] + bd[v];
        out[(long long)b * V + v] = __expf(val - M) * Sinv;
    }
}

// ---------------------------------------------------------------------------
// kernel_launch
// ---------------------------------------------------------------------------
extern "C" void kernel_launch(void* const* d_in, const int* in_sizes, int n_in,
                              void* d_out, int out_size)
{
    const float* enc     = (const float*)d_in[0];
    const float* word    = (const float*)d_in[1];
    const float* h0      = (const float*)d_in[2];
    const float* c0      = (const float*)d_in[3];
    const float* persona = (const float*)d_in[4];
    const float* W1      = (const float*)d_in[5];
    const float* U1      = (const float*)d_in[6];
    const float* b1      = (const float*)d_in[7];
    const float* W2      = (const float*)d_in[8];
    const float* U2      = (const float*)d_in[9];
    const float* b2      = (const float*)d_in[10];
    const float* W3      = (const float*)d_in[11];
    const float* U3      = (const float*)d_in[12];
    const float* b3      = (const float*)d_in[13];
    const float* W4      = (const float*)d_in[14];
    const float* U4      = (const float*)d_in[15];
    const float* b4      = (const float*)d_in[16];
    const float* Wd      = (const float*)d_in[17];
    const float* bd      = (const float*)d_in[18];
    const int*   speaker = (const int*)d_in[19];
    float* out = (float*)d_out;

    void *pz, *pc, *pl, *pxh, *pxl, *phh, *phl;
    cudaGetSymbolAddress(&pz, g_zpart);
    cudaGetSymbolAddress(&pc, g_cbuf);
    cudaGetSymbolAddress(&pl, g_logits);
    cudaGetSymbolAddress(&pxh, g_x1h);
    cudaGetSymbolAddress(&pxl, g_x1l);
    cudaGetSymbolAddress(&phh, g_hh);
    cudaGetSymbolAddress(&phl, g_hl);
    float* zp = (float*)pz;
    float* cb = (float*)pc;
    float* lg = (float*)pl;
    __nv_bfloat16* x1h = (__nv_bfloat16*)pxh;
    __nv_bfloat16* x1l = (__nv_bfloat16*)pxl;
    __nv_bfloat16* hh0 = (__nv_bfloat16*)phh;
    __nv_bfloat16* hh1 = hh0 + Bsz * Hdim;
    __nv_bfloat16* hl0 = (__nv_bfloat16*)phl;
    __nv_bfloat16* hl1 = hl0 + Bsz * Hdim;
    float* c1b = cb;
    float* c2b = cb + Bsz * Hdim;

    // 0) layer-1 A -> bf16 hi/lo planes
    xconv_kernel<<<(Bsz * K1v / 8 + 127) / 128, 128>>>(
        enc, word, persona, h0, speaker, x1h, x1l);

    // 1) layer 1 (fused gates): K=11776, 8 splits of 1472, grid 32x8=256
    mma_gemm_kernel<K1v, false, 8><<<dim3(32, 8), 128>>>(
        x1h, x1l, W1, U1, 11264, 1472, G4H, zp,
        b1, c0, c1b, (uint32_t*)hh0, (uint32_t*)hl0, nullptr, nullptr);

    // 2) layers 2..4 (fused gates): K=1024, 8 splits of 128, grid 32x8=256
    mma_gemm_kernel<Hdim, true, 8><<<dim3(32, 8), 128>>>(
        hh0, hl0, W2, U2, 512, 128, G4H, zp,
        b2, c1b, c2b, (uint32_t*)hh1, (uint32_t*)hl1, nullptr, nullptr);

    mma_gemm_kernel<Hdim, true, 8><<<dim3(32, 8), 128>>>(
        hh1, hl1, W3, U3, 512, 128, G4H, zp,
        b3, c2b, c1b, (uint32_t*)hh0, (uint32_t*)hl0, nullptr, nullptr);

    mma_gemm_kernel<Hdim, true, 8><<<dim3(32, 8), 128>>>(
        hh0, hl0, W4, U4, 512, 128, G4H, zp,
        b4, c1b, c2b, (uint32_t*)hh1, (uint32_t*)hl1,
        out + (long long)Bsz * Vdim,
        out + (long long)Bsz * Vdim + Bsz * Hdim);

    // 3) decoder: logits = h4 @ Wd, grid 500, no split-K, no fusion
    mma_gemm_kernel<Hdim, true, 0><<<dim3(500, 1), 128>>>(
        hh1, hl1, Wd, Wd, 1 << 30, 512, Vdim, lg,
        nullptr, nullptr, nullptr, nullptr, nullptr, nullptr, nullptr);

    // 4) softmax -> probs
    softmax_kernel<<<Bsz, 512>>>(lg, bd, out);
}

// round 15
// speedup vs baseline: 1.3502x; 1.3502x over previous
#include <cuda_runtime.h>
#include <cuda_bf16.h>
#include <cstdint>

// ---------------------------------------------------------------------------
// Problem constants: B=64, S=20, E=512, H=512, V=32000, C=1000
//   D1 = 11264, virtual K1 = 11776 = [enc|word|persona|h0], 4H = 2048
// ---------------------------------------------------------------------------
#define Bsz   64
#define Hdim  512
#define G4H   2048
#define Vdim  32000
#define K1v   11776

static __device__ float g_zpart[8 * Bsz * G4H];            // 4.2 MB (8 slices)
static __device__ float g_cbuf[2][Bsz * Hdim];
static __device__ float g_logits[Bsz * Vdim];              // 8.2 MB
static __device__ __nv_bfloat16 g_x1h[Bsz * K1v];          // layer-1 A hi
static __device__ __nv_bfloat16 g_x1l[Bsz * K1v];          // layer-1 A lo
static __device__ __nv_bfloat16 g_hh[2][Bsz * Hdim];       // h bf16 hi
static __device__ __nv_bfloat16 g_hl[2][Bsz * Hdim];       // h bf16 lo
static __device__ int g_bar1 = 0;                          // grid barrier arrive
static __device__ int g_bar2 = 0;                          // grid barrier depart

__device__ __forceinline__ float sigmoidf_fast(float x) {
    return 1.0f / (1.0f + __expf(-x));
}
__device__ __forceinline__ uint32_t smem_u32(const void* p) {
    uint32_t a;
    asm("{ .reg .u64 t; cvta.to.shared.u64 t, %1; cvt.u32.u64 %0, t; }"
        : "=r"(a) : "l"(p));
    return a;
}
__device__ __forceinline__ void ldsm4(uint32_t* r, uint32_t addr) {
    asm volatile("ldmatrix.sync.aligned.m8n8.x4.shared.b16 {%0,%1,%2,%3}, [%4];"
                 : "=r"(r[0]), "=r"(r[1]), "=r"(r[2]), "=r"(r[3]) : "r"(addr));
}
__device__ __forceinline__ void ldsm4t(uint32_t* r, uint32_t addr) {
    asm volatile("ldmatrix.sync.aligned.m8n8.x4.trans.shared.b16 {%0,%1,%2,%3}, [%4];"
                 : "=r"(r[0]), "=r"(r[1]), "=r"(r[2]), "=r"(r[3]) : "r"(addr));
}
__device__ __forceinline__ void mma16816(float* d, const uint32_t* a,
                                         uint32_t b0, uint32_t b1) {
    asm volatile(
        "mma.sync.aligned.m16n8k16.row.col.f32.bf16.bf16.f32 "
        "{%0,%1,%2,%3}, {%4,%5,%6,%7}, {%8,%9}, {%0,%1,%2,%3};"
        : "+f"(d[0]), "+f"(d[1]), "+f"(d[2]), "+f"(d[3])
        : "r"(a[0]), "r"(a[1]), "r"(a[2]), "r"(a[3]), "r"(b0), "r"(b1));
}
// Dekker split of 2 floats -> packed bf16x2 hi + lo (rn-exact vs element-wise)
__device__ __forceinline__ void dek2(float x, float y, uint32_t& hp, uint32_t& lp) {
    asm("cvt.rn.bf16x2.f32 %0, %1, %2;" : "=r"(hp) : "f"(y), "f"(x));
    float fx = __uint_as_float(hp << 16);
    float fy = __uint_as_float(hp & 0xFFFF0000u);
    asm("cvt.rn.bf16x2.f32 %0, %1, %2;" : "=r"(lp) : "f"(y - fy), "f"(x - fx));
}

// ---------------------------------------------------------------------------
// xconv: build layer-1 A = [enc|word|persona[spk]|h0] as bf16 hi/lo planes.
// ---------------------------------------------------------------------------
__global__ void xconv_kernel(const float* __restrict__ enc,
                             const float* __restrict__ word,
                             const float* __restrict__ persona,
                             const float* __restrict__ h0,
                             const int* __restrict__ speaker,
                             __nv_bfloat16* __restrict__ xh,
                             __nv_bfloat16* __restrict__ xl)
{
    int idx = blockIdx.x * 128 + threadIdx.x;      // < 94208
    int row = idx / (K1v / 8);
    int q = (idx - row * (K1v / 8)) * 8;
    const float* p;
    if (q < 10240)       p = enc + (long long)row * 10240 + q;
    else if (q < 10752)  p = word + (long long)row * 512 + (q - 10240);
    else if (q < 11264)  p = persona + (long long)speaker[row] * 512 + (q - 10752);
    else                 p = h0 + (long long)row * 512 + (q - 11264);
    float4 a = *reinterpret_cast<const float4*>(p);
    float4 b = *reinterpret_cast<const float4*>(p + 4);
    uint32_t h0p, l0p, h1p, l1p, h2p, l2p, h3p, l3p;
    dek2(a.x, a.y, h0p, l0p);
    dek2(a.z, a.w, h1p, l1p);
    dek2(b.x, b.y, h2p, l2p);
    dek2(b.z, b.w, h3p, l3p);
    long long o = (long long)row * K1v + q;
    *reinterpret_cast<uint4*>(xh + o) = make_uint4(h0p, h1p, h2p, h3p);
    *reinterpret_cast<uint4*>(xl + o) = make_uint4(l0p, l1p, l2p, l3p);
}

// ---------------------------------------------------------------------------
// bf16 Dekker-split warp-MMA GEMM with SCALARIZED depth-2 register prefetch,
// optionally FUSED with the LSTM gate reduction via an in-kernel grid barrier
// (NSL > 0; requires grid <= 296 co-resident CTAs at 2 CTA/SM).
// A: preconverted bf16 hi/lo planes. W: fp32, converted in-loader.
// Main loop unrolled x2 so every register-set/buffer index is a literal
// (NT must be even). Tile t lives in smem buf (t&1) and reg set (t&1).
// ---------------------------------------------------------------------------
template<int XSTRIDE, bool WRAP, int NSL>
__global__ __launch_bounds__(128, 2) void mma_gemm_kernel(
    const __nv_bfloat16* __restrict__ Xh, const __nv_bfloat16* __restrict__ Xl,
    const float* __restrict__ Wa, const float* __restrict__ Wb, int wsplit,
    int kc, int N, float* __restrict__ Zall,
    const float* __restrict__ bias, const float* __restrict__ c_prev,
    float* __restrict__ c_new,
    uint32_t* __restrict__ hh_out, uint32_t* __restrict__ hl_out,
    float* __restrict__ h_mir, float* __restrict__ c_mir)
{
    __shared__ __align__(16) __nv_bfloat16 Ah[2][64][40];  // stride 80B
    __shared__ __align__(16) __nv_bfloat16 Al[2][64][40];
    __shared__ __align__(16) __nv_bfloat16 Bh[2][32][72];  // stride 144B
    __shared__ __align__(16) __nv_bfloat16 Bl[2][32][72];

    const int tid = threadIdx.x;
    const int lane = tid & 31;
    const int warp = tid >> 5;
    const int n0 = blockIdx.x * 64;
    const int sp = blockIdx.y;
    const int k0 = sp * kc;
    float* Z = Zall + (long long)sp * 64 * N;

    const int xm = tid >> 1;
    const int xh2 = (tid & 1) * 16;
    const __nv_bfloat16* xhp = Xh + (long long)xm * XSTRIDE;
    const __nv_bfloat16* xlp = Xl + (long long)xm * XSTRIDE;
    const int bk = tid >> 2;
    const int bn = (tid & 3) * 16;

    // two EXPLICIT register sets (no runtime-indexed arrays -> no spills)
    uint4 avh0_0, avh1_0, avl0_0, avl1_0;
    uint4 avh0_1, avh1_1, avl0_1, avl1_1;
    float4 br_0[4], br_1[4];

#define LOAD_A(t, S) do {                                                   \
    int kg = k0 + (t) * 32 + xh2;                                           \
    if (WRAP) kg &= 511;                                                    \
    avh0_##S = *reinterpret_cast<const uint4*>(xhp + kg);                   \
    avh1_##S = *reinterpret_cast<const uint4*>(xhp + kg + 8);               \
    avl0_##S = *reinterpret_cast<const uint4*>(xlp + kg);                   \
    avl1_##S = *reinterpret_cast<const uint4*>(xlp + kg + 8);               \
} while (0)
#define LOAD_B(t, S) do {                                                   \
    int r = k0 + (t) * 32 + bk;                                             \
    const float* p = (r < wsplit) ? (Wa + (long long)r * N)                 \
                                  : (Wb + (long long)(r - wsplit) * N);     \
    br_##S[0] = *reinterpret_cast<const float4*>(p + n0 + bn);              \
    br_##S[1] = *reinterpret_cast<const float4*>(p + n0 + bn + 4);          \
    br_##S[2] = *reinterpret_cast<const float4*>(p + n0 + bn + 8);          \
    br_##S[3] = *reinterpret_cast<const float4*>(p + n0 + bn + 12);         \
} while (0)
#define STORE_A(S) do {                                                     \
    *reinterpret_cast<uint4*>(&Ah[S][xm][xh2])     = avh0_##S;              \
    *reinterpret_cast<uint4*>(&Ah[S][xm][xh2 + 8]) = avh1_##S;              \
    *reinterpret_cast<uint4*>(&Al[S][xm][xh2])     = avl0_##S;              \
    *reinterpret_cast<uint4*>(&Al[S][xm][xh2 + 8]) = avl1_##S;              \
} while (0)
#define STORE_B(S) do {                                                     \
    _Pragma("unroll")                                                       \
    for (int i = 0; i < 4; i++) {                                           \
        float4 v = br_##S[i];                                               \
        uint32_t h01, l01, h23, l23;                                        \
        dek2(v.x, v.y, h01, l01);                                           \
        dek2(v.z, v.w, h23, l23);                                           \
        *reinterpret_cast<uint2*>(&Bh[S][bk][bn + i * 4]) = make_uint2(h01, h23); \
        *reinterpret_cast<uint2*>(&Bl[S][bk][bn + i * 4]) = make_uint2(l01, l23); \
    }                                                                       \
} while (0)

    float acc[4][2][4];
#pragma unroll
    for (int mt = 0; mt < 4; mt++)
#pragma unroll
        for (int nt = 0; nt < 2; nt++)
#pragma unroll
            for (int e = 0; e < 4; e++) acc[mt][nt][e] = 0.0f;

    const int nw = warp * 16;
    const int lr = lane & 15;
    const int lc = (lane >> 4) * 8;

#define COMPUTE(BUF) do {                                                   \
    _Pragma("unroll")                                                       \
    for (int s = 0; s < 2; s++) {                                           \
        uint32_t bhf[4], blf[4];                                            \
        ldsm4t(bhf, smem_u32(&Bh[BUF][s * 16 + lr][nw + lc]));              \
        ldsm4t(blf, smem_u32(&Bl[BUF][s * 16 + lr][nw + lc]));              \
        _Pragma("unroll")                                                   \
        for (int mt = 0; mt < 4; mt++) {                                    \
            uint32_t ahf[4], alf[4];                                        \
            ldsm4(ahf, smem_u32(&Ah[BUF][mt * 16 + lr][s * 16 + lc]));      \
            ldsm4(alf, smem_u32(&Al[BUF][mt * 16 + lr][s * 16 + lc]));      \
            mma16816(acc[mt][0], ahf, bhf[0], bhf[1]);                      \
            mma16816(acc[mt][1], ahf, bhf[2], bhf[3]);                      \
            mma16816(acc[mt][0], ahf, blf[0], blf[1]);                      \
            mma16816(acc[mt][1], ahf, blf[2], blf[3]);                      \
            mma16816(acc[mt][0], alf, bhf[0], bhf[1]);                      \
            mma16816(acc[mt][1], alf, bhf[2], bhf[3]);                      \
        }                                                                   \
    }                                                                       \
} while (0)

    const int NT = kc >> 5;     // BK = 32; NT is even for all call sites
    // prologue: tile 0 -> smem buf0; tile 1 loads in flight (set 1)
    LOAD_A(0, 0); LOAD_B(0, 0);
    STORE_A(0); STORE_B(0);
    __syncthreads();
    LOAD_A(1, 1); LOAD_B(1, 1);

    for (int t = 0; t < NT; t += 2) {
        // ---- tile t (buf/set 0) ----
        if (t + 2 < NT) { LOAD_A(t + 2, 0); LOAD_B(t + 2, 0); }
        COMPUTE(0);
        STORE_A(1); STORE_B(1);        // tile t+1 -> buf1
        __syncthreads();
        // ---- tile t+1 (buf/set 1) ----
        if (t + 3 < NT) { LOAD_A(t + 3, 1); LOAD_B(t + 3, 1); }
        COMPUTE(1);
        if (t + 2 < NT) { STORE_A(0); STORE_B(0); }   // tile t+2 -> buf0
        __syncthreads();
    }

    // GEMM epilogue: write split-K partials
#pragma unroll
    for (int mt = 0; mt < 4; mt++)
#pragma unroll
        for (int nt = 0; nt < 2; nt++) {
            int row = mt * 16 + (lane >> 2);
            int col = n0 + nw + nt * 8 + (lane & 3) * 2;
            *reinterpret_cast<float2*>(&Z[(long long)row * N + col]) =
                make_float2(acc[mt][nt][0], acc[mt][nt][1]);
            *reinterpret_cast<float2*>(&Z[(long long)(row + 8) * N + col]) =
                make_float2(acc[mt][nt][2], acc[mt][nt][3]);
        }

    if (NSL > 0) {
        // ---- grid barrier (all CTAs co-resident by construction) ----
        const int G = gridDim.x * gridDim.y;
        __threadfence();
        __syncthreads();
        if (tid == 0) {
            atomicAdd(&g_bar1, 1);
            while (*(volatile int*)&g_bar1 < G) {}
        }
        __syncthreads();
        __threadfence();

        // ---- phase 2: gates over all slices ----
        int gid = (blockIdx.y * gridDim.x + blockIdx.x) * 128 + tid;
        if (gid < Bsz * (Hdim / 2)) {
            int bt = gid >> 8;
            int j = (gid & 255) * 2;
            float2 zi = *reinterpret_cast<const float2*>(bias + j);
            float2 zf = *reinterpret_cast<const float2*>(bias + 512 + j);
            float2 zg = *reinterpret_cast<const float2*>(bias + 1024 + j);
            float2 zo = *reinterpret_cast<const float2*>(bias + 1536 + j);
            const float* p = Zall + (long long)bt * G4H + j;
#pragma unroll
            for (int s = 0; s < NSL; s++) {
                const float* q = p + (long long)s * Bsz * G4H;
                float2 a = *reinterpret_cast<const float2*>(q);
                float2 b = *reinterpret_cast<const float2*>(q + 512);
                float2 c = *reinterpret_cast<const float2*>(q + 1024);
                float2 d = *reinterpret_cast<const float2*>(q + 1536);
                zi.x += a.x; zi.y += a.y;
                zf.x += b.x; zf.y += b.y;
                zg.x += c.x; zg.y += c.y;
                zo.x += d.x; zo.y += d.y;
            }
            int idx = bt * Hdim + j;
            float2 cp = *reinterpret_cast<const float2*>(c_prev + idx);
            float2 cv, hv;
            cv.x = sigmoidf_fast(zf.x) * cp.x + sigmoidf_fast(zi.x) * fmaxf(zg.x, 0.0f);
            cv.y = sigmoidf_fast(zf.y) * cp.y + sigmoidf_fast(zi.y) * fmaxf(zg.y, 0.0f);
            hv.x = sigmoidf_fast(zo.x) * fmaxf(cv.x, 0.0f);
            hv.y = sigmoidf_fast(zo.y) * fmaxf(cv.y, 0.0f);
            *reinterpret_cast<float2*>(c_new + idx) = cv;
            uint32_t hp, lp;
            dek2(hv.x, hv.y, hp, lp);
            hh_out[gid] = hp;
            hl_out[gid] = lp;
            if (h_mir) {
                *reinterpret_cast<float2*>(h_mir + idx) = hv;
                *reinterpret_cast<float2*>(c_mir + idx) = cv;
            }
        }

        // ---- depart barrier + counter reset (CTA (0,0)) ----
        __threadfence();
        __syncthreads();
        if (tid == 0) {
            atomicAdd(&g_bar2, 1);
            if (blockIdx.x == 0 && blockIdx.y == 0) {
                while (*(volatile int*)&g_bar2 < G) {}
                atomicExch(&g_bar1, 0);
                atomicExch(&g_bar2, 0);
            }
        }
    }
#undef LOAD_A
#undef LOAD_B
#undef STORE_A
#undef STORE_B
#undef COMPUTE
}

// ---------------------------------------------------------------------------
// Softmax over V=32000 per batch row
// ---------------------------------------------------------------------------
__global__ void softmax_kernel(const float* __restrict__ L,
                               const float* __restrict__ bd,
                               float* __restrict__ out)
{
    const int V = Vdim;
    int b = blockIdx.x;
    int tid = threadIdx.x;
    const float* r0 = L + (long long)b * V;

    float m = -1e30f, s = 0.0f;
    for (int v = tid; v < V; v += 512) {
        float val = r0[v] + bd[v];
        float nm = fmaxf(m, val);
        s = s * __expf(m - nm) + __expf(val - nm);
        m = nm;
    }
    __shared__ float sm[512], ss[512];
    sm[tid] = m; ss[tid] = s;
    __syncthreads();
    for (int st = 256; st > 0; st >>= 1) {
        if (tid < st) {
            float m2 = sm[tid + st], s2 = ss[tid + st];
            float nm = fmaxf(sm[tid], m2);
            ss[tid] = ss[tid] * __expf(sm[tid] - nm) + s2 * __expf(m2 - nm);
            sm[tid] = nm;
        }
        __syncthreads();
    }
    float M = sm[0];
    float Sinv = 1.0f / ss[0];
    for (int v = tid; v < V; v += 512) {
        float val = r0[v] + bd[v];
        out[(long long)b * V + v] = __expf(val - M) * Sinv;
    }
}

// ---------------------------------------------------------------------------
// kernel_launch
// ---------------------------------------------------------------------------
extern "C" void kernel_launch(void* const* d_in, const int* in_sizes, int n_in,
                              void* d_out, int out_size)
{
    const float* enc     = (const float*)d_in[0];
    const float* word    = (const float*)d_in[1];
    const float* h0      = (const float*)d_in[2];
    const float* c0      = (const float*)d_in[3];
    const float* persona = (const float*)d_in[4];
    const float* W1      = (const float*)d_in[5];
    const float* U1      = (const float*)d_in[6];
    const float* b1      = (const float*)d_in[7];
    const float* W2      = (const float*)d_in[8];
    const float* U2      = (const float*)d_in[9];
    const float* b2      = (const float*)d_in[10];
    const float* W3      = (const float*)d_in[11];
    const float* U3      = (const float*)d_in[12];
    const float* b3      = (const float*)d_in[13];
    const float* W4      = (const float*)d_in[14];
    const float* U4      = (const float*)d_in[15];
    const float* b4      = (const float*)d_in[16];
    const float* Wd      = (const float*)d_in[17];
    const float* bd      = (const float*)d_in[18];
    const int*   speaker = (const int*)d_in[19];
    float* out = (float*)d_out;

    void *pz, *pc, *pl, *pxh, *pxl, *phh, *phl;
    cudaGetSymbolAddress(&pz, g_zpart);
    cudaGetSymbolAddress(&pc, g_cbuf);
    cudaGetSymbolAddress(&pl, g_logits);
    cudaGetSymbolAddress(&pxh, g_x1h);
    cudaGetSymbolAddress(&pxl, g_x1l);
    cudaGetSymbolAddress(&phh, g_hh);
    cudaGetSymbolAddress(&phl, g_hl);
    float* zp = (float*)pz;
    float* cb = (float*)pc;
    float* lg = (float*)pl;
    __nv_bfloat16* x1h = (__nv_bfloat16*)pxh;
    __nv_bfloat16* x1l = (__nv_bfloat16*)pxl;
    __nv_bfloat16* hh0 = (__nv_bfloat16*)phh;
    __nv_bfloat16* hh1 = hh0 + Bsz * Hdim;
    __nv_bfloat16* hl0 = (__nv_bfloat16*)phl;
    __nv_bfloat16* hl1 = hl0 + Bsz * Hdim;
    float* c1b = cb;
    float* c2b = cb + Bsz * Hdim;

    // 0) layer-1 A -> bf16 hi/lo planes
    xconv_kernel<<<(Bsz * K1v / 8 + 127) / 128, 128>>>(
        enc, word, persona, h0, speaker, x1h, x1l);

    // 1) layer 1 (fused gates): K=11776, 8 splits of 1472 (NT=46), grid 32x8
    mma_gemm_kernel<K1v, false, 8><<<dim3(32, 8), 128>>>(
        x1h, x1l, W1, U1, 11264, 1472, G4H, zp,
        b1, c0, c1b, (uint32_t*)hh0, (uint32_t*)hl0, nullptr, nullptr);

    // 2) layers 2..4 (fused gates): K=1024, 8 splits of 128 (NT=4), grid 32x8
    mma_gemm_kernel<Hdim, true, 8><<<dim3(32, 8), 128>>>(
        hh0, hl0, W2, U2, 512, 128, G4H, zp,
        b2, c1b, c2b, (uint32_t*)hh1, (uint32_t*)hl1, nullptr, nullptr);

    mma_gemm_kernel<Hdim, true, 8><<<dim3(32, 8), 128>>>(
        hh1, hl1, W3, U3, 512, 128, G4H, zp,
        b3, c2b, c1b, (uint32_t*)hh0, (uint32_t*)hl0, nullptr, nullptr);

    mma_gemm_kernel<Hdim, true, 8><<<dim3(32, 8), 128>>>(
        hh0, hl0, W4, U4, 512, 128, G4H, zp,
        b4, c1b, c2b, (uint32_t*)hh1, (uint32_t*)hl1,
        out + (long long)Bsz * Vdim,
        out + (long long)Bsz * Vdim + Bsz * Hdim);

    // 3) decoder: logits = h4 @ Wd, grid 500, NT=16, no split-K, no fusion
    mma_gemm_kernel<Hdim, true, 0><<<dim3(500, 1), 128>>>(
        hh1, hl1, Wd, Wd, 1 << 30, 512, Vdim, lg,
        nullptr, nullptr, nullptr, nullptr, nullptr, nullptr, nullptr);

    // 4) softmax -> probs
    softmax_kernel<<<Bsz, 512>>>(lg, bd, out);
}